// round 3
// baseline (speedup 1.0000x reference)
#include <cuda_runtime.h>
#include <math.h>

// Shapes
#define NN 256   // node_num
#define SS 64    // sensor_num
#define WWIN 256 // slide_win
#define HH 32    // gru hid

// ---------------- scratch (device globals) ------------------------------------
__device__ float g_WhF[NN*SS*WWIN];
__device__ float g_WhT[NN*WWIN*SS];
__device__ float g_Tat[NN*WWIN*SS];
__device__ float g_cat[NN*SS*3*WWIN];
__device__ float g_PF[NN*SS*SS];
__device__ float g_PT[NN*WWIN*WWIN];
__device__ float g_gi[NN*SS*96];
__device__ float g_gru[NN*SS*HH];
__device__ float g_ct[NN*SS];
__device__ float g_cat2[NN*2*SS];
__device__ float g_Wh2[NN*SS];
__device__ float g_WhO[NN*SS];
__device__ float g_WhO1[NN*SS];
__device__ float g_F1[NN*WWIN];
__device__ float g_F2[NN*WWIN];

// ---------------- f32x2 packed-math helpers (B300) ----------------------------
#define FMA_F32X2(d, a, b, c) \
    asm("fma.rn.f32x2 %0, %1, %2, %3;" : "=l"(d) : "l"(a), "l"(b), "l"(c))
#define PACK_F32X2(out, lo, hi) \
    asm("mov.b64 %0, {%1, %2};" : "=l"(out) : "r"(lo), "r"(hi))
#define UNPACK_F32X2(lo, hi, in) \
    asm("mov.b64 {%0, %1}, %2;" : "=r"(lo), "=r"(hi) : "l"(in))

// ---------------- batched tiled SGEMM with packed f32x2 FMA --------------------
// C[b][m][n] = sum_k A[b,m,k]*B[b,k,n] (+bias) (optional relu)
// 128 threads, 8x8 per thread, BK=16. B tile stored value-duplicated so one
// LDS.128 yields two broadcast f32x2 pairs. A tile read as ulonglong2 -> free
// row-pairs. Requires M % BM == 0, K % 16 == 0. N guarded.
template<int BM, int BN>
__global__ void __launch_bounds__(128) gemm_f32x2(
    const float* __restrict__ A, const float* __restrict__ B,
    const float* __restrict__ bias, float* __restrict__ C,
    int M, int N, int K,
    long long sAb, int sAm, int sAk,
    long long sBb, int sBk, int sBn,
    long long sCb, int sCm, int biasStride, int doRelu)
{
    constexpr int TX = BN / 8;          // threads in col dim
    constexpr int LA = BM * 16 / 128;   // A elems per thread per tile
    constexpr int LB = BN * 16 / 128;   // B elems per thread per tile

    int b  = blockIdx.z;
    int m0 = blockIdx.y * BM;
    int n0 = blockIdx.x * BN;
    const float* Ab = A + (size_t)b * sAb;
    const float* Bb = B + (size_t)b * sBb;
    float*       Cb = C + (size_t)b * sCb;

    __shared__ float As[16][BM];
    __shared__ float Bsd[16][2 * BN];   // duplicated: [kk][2n]=[kk][2n+1]=B[kk][n]

    int tid = threadIdx.x;
    int tx = tid % TX, ty = tid / TX;
    int r0 = ty * 8, c0 = tx * 8;
    bool aK1 = (sAk == 1);
    bool bN1 = (sBn == 1);

    unsigned long long acc2[4][8];
    #pragma unroll
    for (int p = 0; p < 4; p++)
        #pragma unroll
        for (int j = 0; j < 8; j++) acc2[p][j] = 0ull;

    for (int k0 = 0; k0 < K; k0 += 16) {
        // ---- load A tile ----
        if (aK1) {
            #pragma unroll
            for (int l = 0; l < LA; l++) {
                int e = tid + l * 128;
                int m = e >> 4, kk = e & 15;
                As[kk][m] = Ab[(size_t)(m0 + m) * sAm + (k0 + kk)];
            }
        } else {  // sAm == 1
            #pragma unroll
            for (int l = 0; l < LA; l++) {
                int e = tid + l * 128;
                int m = e % BM, kk = e / BM;
                As[kk][m] = Ab[(size_t)(m0 + m) + (size_t)(k0 + kk) * sAk];
            }
        }
        // ---- load B tile (duplicated) ----
        if (bN1) {
            #pragma unroll
            for (int l = 0; l < LB; l++) {
                int e = tid + l * 128;
                int n = e % BN, kk = e / BN;
                int gn = n0 + n;
                float v = (gn < N) ? Bb[(size_t)(k0 + kk) * sBk + gn] : 0.f;
                *(float2*)&Bsd[kk][2 * n] = make_float2(v, v);
            }
        } else {  // sBk == 1
            #pragma unroll
            for (int l = 0; l < LB; l++) {
                int e = tid + l * 128;
                int kk = e & 15, n = e >> 4;
                int gn = n0 + n;
                float v = (gn < N) ? Bb[(size_t)(k0 + kk) + (size_t)gn * sBn] : 0.f;
                *(float2*)&Bsd[kk][2 * n] = make_float2(v, v);
            }
        }
        __syncthreads();

        #pragma unroll
        for (int kk = 0; kk < 16; kk++) {
            ulonglong2 a01 = *(const ulonglong2*)&As[kk][r0];
            ulonglong2 a23 = *(const ulonglong2*)&As[kk][r0 + 4];
            unsigned long long a2[4] = {a01.x, a01.y, a23.x, a23.y};
            ulonglong2 b0 = *(const ulonglong2*)&Bsd[kk][2 * c0];
            ulonglong2 b1 = *(const ulonglong2*)&Bsd[kk][2 * c0 + 4];
            ulonglong2 b2 = *(const ulonglong2*)&Bsd[kk][2 * c0 + 8];
            ulonglong2 b3 = *(const ulonglong2*)&Bsd[kk][2 * c0 + 12];
            unsigned long long bd[8] = {b0.x, b0.y, b1.x, b1.y, b2.x, b2.y, b3.x, b3.y};
            #pragma unroll
            for (int p = 0; p < 4; p++)
                #pragma unroll
                for (int j = 0; j < 8; j++)
                    FMA_F32X2(acc2[p][j], a2[p], bd[j], acc2[p][j]);
        }
        __syncthreads();
    }

    // ---- epilogue ----
    #pragma unroll
    for (int p = 0; p < 4; p++) {
        int gm0 = m0 + r0 + 2 * p;
        float v0[8], v1[8];
        #pragma unroll
        for (int j = 0; j < 8; j++) {
            unsigned int ul, uh;
            UNPACK_F32X2(ul, uh, acc2[p][j]);
            v0[j] = __uint_as_float(ul);
            v1[j] = __uint_as_float(uh);
        }
        #pragma unroll
        for (int j = 0; j < 8; j++) {
            int gn = n0 + c0 + j;
            if (gn < N) {
                float bv = bias ? bias[(size_t)b * biasStride + gn] : 0.f;
                float a = v0[j] + bv, c = v1[j] + bv;
                if (doRelu) { a = fmaxf(a, 0.f); c = fmaxf(c, 0.f); }
                Cb[(size_t)gm0 * sCm + gn] = a;
                Cb[(size_t)(gm0 + 1) * sCm + gn] = c;
            }
        }
    }
}

// ---------------- GAT: f1/f2 projections (one warp per (b,m) row) -------------
__global__ void gat_f12(const float* __restrict__ Wh, const float* __restrict__ a,
                        float* __restrict__ F1, float* __restrict__ F2,
                        int M, int dout, long long aStride, int total)
{
    int gw = blockIdx.x * (blockDim.x >> 5) + (threadIdx.x >> 5);
    int lane = threadIdx.x & 31;
    if (gw >= total) return;
    int b = gw / M, m = gw % M;
    const float* whr = Wh + ((size_t)b * M + m) * dout;
    const float* ab  = a + (size_t)b * aStride;
    float s1 = 0.f, s2 = 0.f;
    for (int c = lane; c < dout; c += 32) {
        float w = whr[c];
        s1 += w * ab[c];
        s2 += w * ab[dout + c];
    }
    #pragma unroll
    for (int o = 16; o; o >>= 1) {
        s1 += __shfl_xor_sync(0xffffffffu, s1, o);
        s2 += __shfl_xor_sync(0xffffffffu, s2, o);
    }
    if (lane == 0) { F1[(size_t)b * M + m] = s1; F2[(size_t)b * M + m] = s2; }
}

// ---------------- GAT: masked softmax -> P ------------------------------------
__global__ void gat_softmax(const float* __restrict__ F1, const float* __restrict__ F2,
                            const float* __restrict__ adj, long long adjBStride,
                            int M, float* __restrict__ P)
{
    int b = blockIdx.y;
    int warp = threadIdx.x >> 5, lane = threadIdx.x & 31;
    int m = blockIdx.x * 8 + warp;
    __shared__ float pbuf[8][WWIN];
    if (m >= M) return;

    const float* adjrow = adj + (size_t)b * adjBStride + (size_t)m * M;
    const float* F2b = F2 + (size_t)b * M;
    float f1m = F1[(size_t)b * M + m];

    float mx = -3.4e38f;
    for (int k = lane; k < M; k += 32) {
        float e = f1m + F2b[k];
        e = (e >= 0.f) ? e : 0.2f * e;
        float v = (adjrow[k] > 0.f) ? e : -9e15f;
        pbuf[warp][k] = v;
        mx = fmaxf(mx, v);
    }
    #pragma unroll
    for (int o = 16; o; o >>= 1) mx = fmaxf(mx, __shfl_xor_sync(0xffffffffu, mx, o));
    float s = 0.f;
    for (int k = lane; k < M; k += 32) {
        float ex = expf(pbuf[warp][k] - mx);
        pbuf[warp][k] = ex;
        s += ex;
    }
    #pragma unroll
    for (int o = 16; o; o >>= 1) s += __shfl_xor_sync(0xffffffffu, s, o);
    float inv = 1.f / s;
    float* Prow = P + ((size_t)b * M + m) * M;
    for (int k = lane; k < M; k += 32) Prow[k] = pbuf[warp][k] * inv;
}

// ---------------- GAT: softmax + att@Wh (small output GATs) -------------------
__global__ void gat_attn(const float* __restrict__ Wh, const float* __restrict__ F1,
                         const float* __restrict__ F2, const float* __restrict__ adj,
                         long long adjBStride, int M, int dout,
                         float* __restrict__ outp, long long outBStride,
                         long long outOff, int outRowStride, int outColStride)
{
    int b = blockIdx.y;
    int warp = threadIdx.x >> 5, lane = threadIdx.x & 31;
    int m = blockIdx.x * 8 + warp;
    __shared__ float pbuf[8][WWIN];
    if (m >= M) return;

    const float* adjrow = adj + (size_t)b * adjBStride + (size_t)m * M;
    const float* F2b = F2 + (size_t)b * M;
    float f1m = F1[(size_t)b * M + m];

    float mx = -3.4e38f;
    for (int k = lane; k < M; k += 32) {
        float e = f1m + F2b[k];
        e = (e >= 0.f) ? e : 0.2f * e;
        float v = (adjrow[k] > 0.f) ? e : -9e15f;
        pbuf[warp][k] = v;
        mx = fmaxf(mx, v);
    }
    #pragma unroll
    for (int o = 16; o; o >>= 1) mx = fmaxf(mx, __shfl_xor_sync(0xffffffffu, mx, o));
    float s = 0.f;
    for (int k = lane; k < M; k += 32) {
        float ex = expf(pbuf[warp][k] - mx);
        pbuf[warp][k] = ex;
        s += ex;
    }
    #pragma unroll
    for (int o = 16; o; o >>= 1) s += __shfl_xor_sync(0xffffffffu, s, o);
    float inv = 1.f / s;
    __syncwarp();

    const float* Whb = Wh + (size_t)b * M * dout;
    float* ob = outp + (size_t)b * outBStride + outOff + (size_t)m * outRowStride;
    for (int c0 = 0; c0 < dout; c0 += 32) {
        int c = c0 + lane;
        float acc = 0.f;
        for (int k = 0; k < M; k++) acc += pbuf[warp][k] * Whb[(size_t)k * dout + c];
        ob[(size_t)c * outColStride] = acc * inv;
    }
}

// ---------------- transpose Tat[n,w,s] -> cat[n,s,256+w] ----------------------
__global__ void transpose_T(const float* __restrict__ Tat, float* __restrict__ cat)
{
    __shared__ float tile[32][33];
    int n = blockIdx.z;
    int w0 = blockIdx.x * 32, s0 = blockIdx.y * 32;
    int tx = threadIdx.x, ty = threadIdx.y;   // 32x8
    #pragma unroll
    for (int i = 0; i < 32; i += 8)
        tile[ty + i][tx] = Tat[(size_t)n * 16384 + (size_t)(w0 + ty + i) * 64 + s0 + tx];
    __syncthreads();
    #pragma unroll
    for (int i = 0; i < 32; i += 8)
        cat[(size_t)n * 49152 + (size_t)(s0 + ty + i) * 768 + 256 + w0 + tx] = tile[tx][ty + i];
}

// ---------------- copy x into the third slot of cat_at ------------------------
__global__ void copyx(const float* __restrict__ x, float* __restrict__ cat)
{
    int idx = blockIdx.x * blockDim.x + threadIdx.x;
    if (idx >= NN * SS * WWIN) return;
    int w = idx & 255;
    int s = (idx >> 8) & 63;
    int n = idx >> 14;
    cat[((size_t)n * SS + s) * 768 + 512 + w] = x[idx];
}

// ---------------- GRU recurrence ----------------------------------------------
__device__ __forceinline__ float sigmf(float x) { return 1.f / (1.f + expf(-x)); }

__global__ void gru_kernel(const float* __restrict__ giAll,
                           const float* __restrict__ Whh0, const float* __restrict__ bhh0,
                           const float* __restrict__ Wih1, const float* __restrict__ bih1,
                           const float* __restrict__ Whh1, const float* __restrict__ bhh1,
                           const float* __restrict__ Hpre,
                           float* __restrict__ gruOut, float* __restrict__ outCatH)
{
    int n = blockIdx.x;
    int tid = threadIdx.x;                 // 96 threads
    __shared__ float w0[96 * 33], wi1[96 * 33], wh1[96 * 33];
    __shared__ float h0s[32], h1s[32];
    __shared__ float gi0s[96], gh0s[96], gi1s[96], gh1s[96];

    for (int idx = tid; idx < 96 * 32; idx += 96) {
        int g = idx >> 5, j = idx & 31;
        w0 [g * 33 + j] = Whh0[(size_t)n * 3072 + idx];
        wi1[g * 33 + j] = Wih1[(size_t)n * 3072 + idx];
        wh1[g * 33 + j] = Whh1[(size_t)n * 3072 + idx];
    }
    if (tid < 32) {
        h0s[tid] = Hpre[(size_t)n * 32 + tid];
        h1s[tid] = Hpre[8192 + (size_t)n * 32 + tid];
    }
    float bh0v = bhh0[(size_t)n * 96 + tid];
    float bi1v = bih1[(size_t)n * 96 + tid];
    float bh1v = bhh1[(size_t)n * 96 + tid];
    __syncthreads();

    for (int t = 0; t < SS; t++) {
        float acc = bh0v;
        #pragma unroll
        for (int j = 0; j < 32; j++) acc += w0[tid * 33 + j] * h0s[j];
        gh0s[tid] = acc;
        gi0s[tid] = giAll[((size_t)n * SS + t) * 96 + tid];
        __syncthreads();
        if (tid < 32) {
            float r  = sigmf(gi0s[tid]      + gh0s[tid]);
            float z  = sigmf(gi0s[32 + tid] + gh0s[32 + tid]);
            float nn = tanhf(gi0s[64 + tid] + r * gh0s[64 + tid]);
            h0s[tid] = (1.f - z) * nn + z * h0s[tid];
        }
        __syncthreads();
        float a1 = bi1v, a2 = bh1v;
        #pragma unroll
        for (int j = 0; j < 32; j++) {
            a1 += wi1[tid * 33 + j] * h0s[j];
            a2 += wh1[tid * 33 + j] * h1s[j];
        }
        gi1s[tid] = a1; gh1s[tid] = a2;
        __syncthreads();
        if (tid < 32) {
            float r  = sigmf(gi1s[tid]      + gh1s[tid]);
            float z  = sigmf(gi1s[32 + tid] + gh1s[32 + tid]);
            float nn = tanhf(gi1s[64 + tid] + r * gh1s[64 + tid]);
            float h1n = (1.f - z) * nn + z * h1s[tid];
            h1s[tid] = h1n;
            gruOut[((size_t)n * SS + t) * 32 + tid] = h1n;
        }
        __syncthreads();
    }
    if (tid < 32) {
        outCatH[(size_t)n * 32 + tid]        = h0s[tid];
        outCatH[8192 + (size_t)n * 32 + tid] = h1s[tid];
    }
}

// ---------------- fused fc1+fc2+fc3 -------------------------------------------
__global__ void fc_fused(const float* __restrict__ gru,
                         const float* __restrict__ W1, const float* __restrict__ b1,
                         const float* __restrict__ W2, const float* __restrict__ b2,
                         const float* __restrict__ w3, const float* __restrict__ b3,
                         float* __restrict__ ct)
{
    int n = blockIdx.x;
    int tid = threadIdx.x;                 // 256
    int warp = tid >> 5, lane = tid & 31;
    __shared__ float W1s[32 * 33], W2s[32 * 33];
    __shared__ float w3s[32], b1s[32], b2s[32];
    __shared__ float xs[8][33];

    for (int idx = tid; idx < 1024; idx += 256) {
        int r = idx >> 5, c = idx & 31;
        W1s[r * 33 + c] = W1[(size_t)n * 1024 + idx];
        W2s[r * 33 + c] = W2[(size_t)n * 1024 + idx];
    }
    if (tid < 32) {
        w3s[tid] = w3[(size_t)n * 32 + tid];
        b1s[tid] = b1[(size_t)n * 32 + tid];
        b2s[tid] = b2[(size_t)n * 32 + tid];
    }
    __syncthreads();
    float b3v = b3[n];

    for (int s = warp; s < 64; s += 8) {
        float xv = gru[((size_t)n * 64 + s) * 32 + lane];
        xs[warp][lane] = xv;
        __syncwarp();
        float h1 = b1s[lane];
        #pragma unroll
        for (int j = 0; j < 32; j++) h1 += W1s[lane * 33 + j] * xs[warp][j];
        h1 = fmaxf(h1, 0.f);
        __syncwarp();
        xs[warp][lane] = h1;
        __syncwarp();
        float h2 = b2s[lane];
        #pragma unroll
        for (int j = 0; j < 32; j++) h2 += W2s[lane * 33 + j] * xs[warp][j];
        h2 = fmaxf(h2, 0.f);
        float p = h2 * w3s[lane];
        #pragma unroll
        for (int o = 16; o; o >>= 1) p += __shfl_xor_sync(0xffffffffu, p, o);
        if (lane == 0) ct[(size_t)n * 64 + s] = p + b3v;
        __syncwarp();
    }
}

// ---------------- launch -------------------------------------------------------
extern "C" void kernel_launch(void* const* d_in, const int* in_sizes, int n_in,
                              void* d_out, int out_size)
{
    const float* x     = (const float*)d_in[0];
    const float* Fadj  = (const float*)d_in[1];
    const float* Tadj  = (const float*)d_in[2];
    const float* adj   = (const float*)d_in[3];
    const float* Hpre  = (const float*)d_in[4];
    const float* FattW = (const float*)d_in[5];
    const float* Fatta = (const float*)d_in[6];
    const float* TattW = (const float*)d_in[7];
    const float* Tatta = (const float*)d_in[8];
    const float* Wih0  = (const float*)d_in[9];
    const float* Whh0  = (const float*)d_in[10];
    const float* bih0  = (const float*)d_in[11];
    const float* bhh0  = (const float*)d_in[12];
    const float* Wih1  = (const float*)d_in[13];
    const float* Whh1  = (const float*)d_in[14];
    const float* bih1  = (const float*)d_in[15];
    const float* bhh1  = (const float*)d_in[16];
    const float* fc1w  = (const float*)d_in[17];
    const float* fc1b  = (const float*)d_in[18];
    const float* fc2w  = (const float*)d_in[19];
    const float* fc2b  = (const float*)d_in[20];
    const float* fc3w  = (const float*)d_in[21];
    const float* fc3b  = (const float*)d_in[22];
    const float* oW    = (const float*)d_in[23];
    const float* oa    = (const float*)d_in[24];
    const float* o1W   = (const float*)d_in[25];
    const float* o1a   = (const float*)d_in[26];
    const float* o2W   = (const float*)d_in[27];
    const float* o2a   = (const float*)d_in[28];
    float* out = (float*)d_out;

    float *WhF, *WhT, *Tat, *cat, *PF, *PT, *gi, *gru, *ct, *cat2, *Wh2, *WhO, *WhO1, *F1, *F2;
    cudaGetSymbolAddress((void**)&WhF,  g_WhF);
    cudaGetSymbolAddress((void**)&WhT,  g_WhT);
    cudaGetSymbolAddress((void**)&Tat,  g_Tat);
    cudaGetSymbolAddress((void**)&cat,  g_cat);
    cudaGetSymbolAddress((void**)&PF,   g_PF);
    cudaGetSymbolAddress((void**)&PT,   g_PT);
    cudaGetSymbolAddress((void**)&gi,   g_gi);
    cudaGetSymbolAddress((void**)&gru,  g_gru);
    cudaGetSymbolAddress((void**)&ct,   g_ct);
    cudaGetSymbolAddress((void**)&cat2, g_cat2);
    cudaGetSymbolAddress((void**)&Wh2,  g_Wh2);
    cudaGetSymbolAddress((void**)&WhO,  g_WhO);
    cudaGetSymbolAddress((void**)&WhO1, g_WhO1);
    cudaGetSymbolAddress((void**)&F1,   g_F1);
    cudaGetSymbolAddress((void**)&F2,   g_F2);

    // ---- Feature GAT ----
    gemm_f32x2<64,128><<<dim3(2, 1, 256), 128>>>(x, FattW, nullptr, WhF, 64, 256, 256,
                                                 16384LL, 256, 1,  65536LL, 256, 1,
                                                 16384LL, 256, 0, 0);
    gat_f12<<<2048, 256>>>(WhF, Fatta, F1, F2, 64, 256, 512LL, 256 * 64);
    gat_softmax<<<dim3(8, 256), 256>>>(F1, F2, Fadj, 4096LL, 64, PF);
    gemm_f32x2<64,128><<<dim3(2, 1, 256), 128>>>(PF, WhF, nullptr, cat, 64, 256, 64,
                                                 4096LL, 64, 1,  16384LL, 256, 1,
                                                 49152LL, 768, 0, 0);

    // ---- Time GAT ----
    gemm_f32x2<128,64><<<dim3(1, 2, 256), 128>>>(x, TattW, nullptr, WhT, 256, 64, 64,
                                                 16384LL, 1, 256,  4096LL, 64, 1,
                                                 16384LL, 64, 0, 0);
    gat_f12<<<8192, 256>>>(WhT, Tatta, F1, F2, 256, 64, 128LL, 256 * 256);
    gat_softmax<<<dim3(32, 256), 256>>>(F1, F2, Tadj, 65536LL, 256, PT);
    gemm_f32x2<128,64><<<dim3(1, 2, 256), 128>>>(PT, WhT, nullptr, Tat, 256, 64, 256,
                                                 65536LL, 256, 1,  16384LL, 64, 1,
                                                 16384LL, 64, 0, 0);
    transpose_T<<<dim3(8, 2, 256), dim3(32, 8)>>>(Tat, cat);

    // ---- x -> cat[:, :, 512:768] ----
    copyx<<<16384, 256>>>(x, cat);

    // ---- GRU input projection ----
    gemm_f32x2<64,128><<<dim3(1, 1, 256), 128>>>(cat, Wih0, bih0, gi, 64, 96, 768,
                                                 49152LL, 768, 1,  73728LL, 1, 768,
                                                 6144LL, 96, 96, 0);

    // ---- GRU recurrence ----
    gru_kernel<<<256, 96>>>(gi, Whh0, bhh0, Wih1, bih1, Whh1, bhh1, Hpre,
                            gru, out + 16384);

    // ---- fused FC stack ----
    fc_fused<<<256, 256>>>(gru, fc1w, fc1b, fc2w, fc2b, fc3w, fc3b, ct);

    // ---- output GAT #1 ----
    gemm_f32x2<128,64><<<dim3(1, 2, 1), 128>>>(ct, oW, nullptr, WhO, 256, 64, 64,
                                               0LL, 64, 1,  0LL, 64, 1,  0LL, 64, 0, 0);
    gat_f12<<<32, 256>>>(WhO, oa, F1, F2, 256, 64, 0LL, 256);
    gat_attn<<<dim3(32, 1), 256>>>(WhO, F1, F2, adj, 0LL, 256, 64,
                                   cat2, 0LL, 0LL, 128, 1);

    // ---- output GAT #2 ----
    gemm_f32x2<128,64><<<dim3(1, 2, 1), 128>>>(ct, o1W, nullptr, WhO1, 256, 64, 64,
                                               0LL, 64, 1,  0LL, 64, 1,  0LL, 64, 0, 0);
    gat_f12<<<32, 256>>>(WhO1, o1a, F1, F2, 256, 64, 0LL, 256);
    gat_attn<<<dim3(32, 1), 256>>>(WhO1, F1, F2, adj, 0LL, 256, 64,
                                   cat2, 0LL, 64LL, 128, 1);

    // ---- final GAT -> d_out ----
    gemm_f32x2<128,64><<<dim3(1, 2, 1), 128>>>(cat2, o2W, nullptr, Wh2, 256, 64, 128,
                                               0LL, 128, 1,  0LL, 64, 1,  0LL, 64, 0, 0);
    gat_f12<<<32, 256>>>(Wh2, o2a, F1, F2, 256, 64, 0LL, 256);
    gat_attn<<<dim3(32, 1), 256>>>(Wh2, F1, F2, adj, 0LL, 256, 64,
                                   out, 0LL, 0LL, 64, 1);
}

// round 4
// speedup vs baseline: 1.7030x; 1.7030x over previous
#include <cuda_runtime.h>
#include <math.h>

// Shapes
#define NN 256   // node_num
#define SS 64    // sensor_num
#define WWIN 256 // slide_win
#define HH 32    // gru hid

// ---------------- scratch (device globals) ------------------------------------
__device__ float g_WhF[NN*SS*WWIN];
__device__ float g_WhT[NN*WWIN*SS];
__device__ float g_Tat[NN*WWIN*SS];
__device__ float g_cat[NN*SS*3*WWIN];
__device__ float g_PF[NN*SS*SS];
__device__ float g_PT[NN*WWIN*WWIN];
__device__ float g_gi[NN*SS*96];
__device__ float g_gru[NN*SS*HH];
__device__ float g_ct[NN*SS];
__device__ float g_cat2[NN*2*SS];
__device__ float g_Wh2[NN*SS];
__device__ float g_WhO[NN*SS];
__device__ float g_WhO1[NN*SS];
__device__ float g_F1[NN*WWIN];
__device__ float g_F2[NN*WWIN];

// ---------------- f32x2 packed-math helpers (B300) ----------------------------
#define FMA_F32X2(d, a, b, c) \
    asm("fma.rn.f32x2 %0, %1, %2, %3;" : "=l"(d) : "l"(a), "l"(b), "l"(c))
#define PACK_F32X2(out, lo, hi) \
    asm("mov.b64 %0, {%1, %2};" : "=l"(out) : "r"(lo), "r"(hi))
#define UNPACK_F32X2(lo, hi, in) \
    asm("mov.b64 {%0, %1}, %2;" : "=r"(lo), "=r"(hi) : "l"(in))

// ---------------- batched tiled SGEMM with packed f32x2 FMA --------------------
// 256 threads, 4 rows x 8 cols per thread, BK=16.
// A pairs come packed straight from smem (ulonglong2); B values duplicated into
// f32x2 broadcast pairs in registers. Requires M % BM == 0, K % 16 == 0.
template<int BM, int BN>
__global__ void __launch_bounds__(256, 2) gemm_p2(
    const float* __restrict__ A, const float* __restrict__ B,
    const float* __restrict__ bias, float* __restrict__ C,
    int M, int N, int K,
    long long sAb, int sAm, int sAk,
    long long sBb, int sBk, int sBn,
    long long sCb, int sCm, int biasStride, int doRelu)
{
    constexpr int TX = BN / 8;          // threads along cols (8 cols each, split 4+4)
    constexpr int LA = BM * 16 / 256;   // A elems per thread per K-tile
    constexpr int LB = BN * 16 / 256;   // B elems per thread per K-tile

    int b  = blockIdx.z;
    int m0 = blockIdx.y * BM;
    int n0 = blockIdx.x * BN;
    const float* Ab = A + (size_t)b * sAb;
    const float* Bb = B + (size_t)b * sBb;
    float*       Cb = C + (size_t)b * sCb;

    __shared__ float As[16][BM];
    __shared__ float Bs[16][BN];

    int tid = threadIdx.x;
    int tx = tid % TX, ty = tid / TX;
    int r0  = ty * 4;                  // 4 consecutive rows -> 2 packed pairs
    int c0a = tx * 4;                  // first 4 cols
    int c0b = BN / 2 + tx * 4;         // second 4 cols
    bool aK1 = (sAk == 1);
    bool bN1 = (sBn == 1);

    unsigned long long acc2[2][8];
    #pragma unroll
    for (int p = 0; p < 2; p++)
        #pragma unroll
        for (int j = 0; j < 8; j++) acc2[p][j] = 0ull;

    auto loadA = [&](int k0, float r[LA]) {
        if (aK1) {
            #pragma unroll
            for (int l = 0; l < LA; l++) {
                int e = tid + l * 256; int m = e >> 4, kk = e & 15;
                r[l] = Ab[(size_t)(m0 + m) * sAm + (k0 + kk)];
            }
        } else {  // sAm == 1
            #pragma unroll
            for (int l = 0; l < LA; l++) {
                int e = tid + l * 256; int m = e % BM, kk = e / BM;
                r[l] = Ab[(size_t)(m0 + m) + (size_t)(k0 + kk) * sAk];
            }
        }
    };
    auto storeA = [&](float r[LA]) {
        if (aK1) {
            #pragma unroll
            for (int l = 0; l < LA; l++) { int e = tid + l * 256; As[e & 15][e >> 4] = r[l]; }
        } else {
            #pragma unroll
            for (int l = 0; l < LA; l++) { int e = tid + l * 256; As[e / BM][e % BM] = r[l]; }
        }
    };
    auto loadB = [&](int k0, float r[LB]) {
        if (bN1) {
            #pragma unroll
            for (int l = 0; l < LB; l++) {
                int e = tid + l * 256; int n = e % BN, kk = e / BN; int gn = n0 + n;
                r[l] = (gn < N) ? Bb[(size_t)(k0 + kk) * sBk + gn] : 0.f;
            }
        } else {  // sBk == 1
            #pragma unroll
            for (int l = 0; l < LB; l++) {
                int e = tid + l * 256; int kk = e & 15, n = e >> 4; int gn = n0 + n;
                r[l] = (gn < N) ? Bb[(size_t)(k0 + kk) + (size_t)gn * sBn] : 0.f;
            }
        }
    };
    auto storeB = [&](float r[LB]) {
        if (bN1) {
            #pragma unroll
            for (int l = 0; l < LB; l++) { int e = tid + l * 256; Bs[e / BN][e % BN] = r[l]; }
        } else {
            #pragma unroll
            for (int l = 0; l < LB; l++) { int e = tid + l * 256; Bs[e & 15][e >> 4] = r[l]; }
        }
    };

    float ra[LA], rb[LB], na[LA], nb[LB];
    loadA(0, ra); loadB(0, rb);

    for (int k0 = 0; k0 < K; k0 += 16) {
        storeA(ra); storeB(rb);
        __syncthreads();
        if (k0 + 16 < K) { loadA(k0 + 16, na); loadB(k0 + 16, nb); }

        #pragma unroll
        for (int kk = 0; kk < 16; kk++) {
            ulonglong2 a01 = *(const ulonglong2*)&As[kk][r0];   // 2 packed row-pairs
            unsigned long long a2[2] = {a01.x, a01.y};
            float4 bA = *(const float4*)&Bs[kk][c0a];
            float4 bB = *(const float4*)&Bs[kk][c0b];
            float bv[8] = {bA.x, bA.y, bA.z, bA.w, bB.x, bB.y, bB.z, bB.w};
            unsigned long long bd[8];
            #pragma unroll
            for (int j = 0; j < 8; j++) {
                unsigned int u = __float_as_uint(bv[j]);
                PACK_F32X2(bd[j], u, u);
            }
            #pragma unroll
            for (int p = 0; p < 2; p++)
                #pragma unroll
                for (int j = 0; j < 8; j++)
                    FMA_F32X2(acc2[p][j], a2[p], bd[j], acc2[p][j]);
        }
        __syncthreads();
        #pragma unroll
        for (int l = 0; l < LA; l++) ra[l] = na[l];
        #pragma unroll
        for (int l = 0; l < LB; l++) rb[l] = nb[l];
    }

    // ---- epilogue ----
    #pragma unroll
    for (int p = 0; p < 2; p++) {
        int gm0 = m0 + r0 + 2 * p;          // pair covers rows gm0, gm0+1
        #pragma unroll
        for (int j = 0; j < 8; j++) {
            int gn = n0 + ((j < 4) ? (c0a + j) : (c0b + j - 4));
            if (gn < N) {
                unsigned int ul, uh;
                UNPACK_F32X2(ul, uh, acc2[p][j]);
                float v0 = __uint_as_float(ul), v1 = __uint_as_float(uh);
                if (bias) {
                    float bv = bias[(size_t)b * biasStride + gn];
                    v0 += bv; v1 += bv;
                }
                if (doRelu) { v0 = fmaxf(v0, 0.f); v1 = fmaxf(v1, 0.f); }
                Cb[(size_t)gm0 * sCm + gn]       = v0;
                Cb[(size_t)(gm0 + 1) * sCm + gn] = v1;
            }
        }
    }
}

// ---------------- GAT: f1/f2 projections (one warp per (b,m) row) -------------
__global__ void gat_f12(const float* __restrict__ Wh, const float* __restrict__ a,
                        float* __restrict__ F1, float* __restrict__ F2,
                        int M, int dout, long long aStride, int total)
{
    int gw = blockIdx.x * (blockDim.x >> 5) + (threadIdx.x >> 5);
    int lane = threadIdx.x & 31;
    if (gw >= total) return;
    int b = gw / M, m = gw % M;
    const float* whr = Wh + ((size_t)b * M + m) * dout;
    const float* ab  = a + (size_t)b * aStride;
    float s1 = 0.f, s2 = 0.f;
    for (int c = lane; c < dout; c += 32) {
        float w = whr[c];
        s1 += w * ab[c];
        s2 += w * ab[dout + c];
    }
    #pragma unroll
    for (int o = 16; o; o >>= 1) {
        s1 += __shfl_xor_sync(0xffffffffu, s1, o);
        s2 += __shfl_xor_sync(0xffffffffu, s2, o);
    }
    if (lane == 0) { F1[(size_t)b * M + m] = s1; F2[(size_t)b * M + m] = s2; }
}

// ---------------- GAT: masked softmax -> P ------------------------------------
__global__ void gat_softmax(const float* __restrict__ F1, const float* __restrict__ F2,
                            const float* __restrict__ adj, long long adjBStride,
                            int M, float* __restrict__ P)
{
    int b = blockIdx.y;
    int warp = threadIdx.x >> 5, lane = threadIdx.x & 31;
    int m = blockIdx.x * 8 + warp;
    __shared__ float pbuf[8][WWIN];
    if (m >= M) return;

    const float* adjrow = adj + (size_t)b * adjBStride + (size_t)m * M;
    const float* F2b = F2 + (size_t)b * M;
    float f1m = F1[(size_t)b * M + m];

    float mx = -3.4e38f;
    for (int k = lane; k < M; k += 32) {
        float e = f1m + F2b[k];
        e = (e >= 0.f) ? e : 0.2f * e;
        float v = (adjrow[k] > 0.f) ? e : -9e15f;
        pbuf[warp][k] = v;
        mx = fmaxf(mx, v);
    }
    #pragma unroll
    for (int o = 16; o; o >>= 1) mx = fmaxf(mx, __shfl_xor_sync(0xffffffffu, mx, o));
    float s = 0.f;
    for (int k = lane; k < M; k += 32) {
        float ex = expf(pbuf[warp][k] - mx);
        pbuf[warp][k] = ex;
        s += ex;
    }
    #pragma unroll
    for (int o = 16; o; o >>= 1) s += __shfl_xor_sync(0xffffffffu, s, o);
    float inv = 1.f / s;
    float* Prow = P + ((size_t)b * M + m) * M;
    for (int k = lane; k < M; k += 32) Prow[k] = pbuf[warp][k] * inv;
}

// ---------------- GAT: softmax + att@Wh (small output GATs) -------------------
__global__ void gat_attn(const float* __restrict__ Wh, const float* __restrict__ F1,
                         const float* __restrict__ F2, const float* __restrict__ adj,
                         long long adjBStride, int M, int dout,
                         float* __restrict__ outp, long long outBStride,
                         long long outOff, int outRowStride, int outColStride)
{
    int b = blockIdx.y;
    int warp = threadIdx.x >> 5, lane = threadIdx.x & 31;
    int m = blockIdx.x * 8 + warp;
    __shared__ float pbuf[8][WWIN];
    if (m >= M) return;

    const float* adjrow = adj + (size_t)b * adjBStride + (size_t)m * M;
    const float* F2b = F2 + (size_t)b * M;
    float f1m = F1[(size_t)b * M + m];

    float mx = -3.4e38f;
    for (int k = lane; k < M; k += 32) {
        float e = f1m + F2b[k];
        e = (e >= 0.f) ? e : 0.2f * e;
        float v = (adjrow[k] > 0.f) ? e : -9e15f;
        pbuf[warp][k] = v;
        mx = fmaxf(mx, v);
    }
    #pragma unroll
    for (int o = 16; o; o >>= 1) mx = fmaxf(mx, __shfl_xor_sync(0xffffffffu, mx, o));
    float s = 0.f;
    for (int k = lane; k < M; k += 32) {
        float ex = expf(pbuf[warp][k] - mx);
        pbuf[warp][k] = ex;
        s += ex;
    }
    #pragma unroll
    for (int o = 16; o; o >>= 1) s += __shfl_xor_sync(0xffffffffu, s, o);
    float inv = 1.f / s;
    __syncwarp();

    const float* Whb = Wh + (size_t)b * M * dout;
    float* ob = outp + (size_t)b * outBStride + outOff + (size_t)m * outRowStride;
    for (int c0 = 0; c0 < dout; c0 += 32) {
        int c = c0 + lane;
        float acc = 0.f;
        for (int k = 0; k < M; k++) acc += pbuf[warp][k] * Whb[(size_t)k * dout + c];
        ob[(size_t)c * outColStride] = acc * inv;
    }
}

// ---------------- transpose Tat[n,w,s] -> cat[n,s,256+w] ----------------------
__global__ void transpose_T(const float* __restrict__ Tat, float* __restrict__ cat)
{
    __shared__ float tile[32][33];
    int n = blockIdx.z;
    int w0 = blockIdx.x * 32, s0 = blockIdx.y * 32;
    int tx = threadIdx.x, ty = threadIdx.y;   // 32x8
    #pragma unroll
    for (int i = 0; i < 32; i += 8)
        tile[ty + i][tx] = Tat[(size_t)n * 16384 + (size_t)(w0 + ty + i) * 64 + s0 + tx];
    __syncthreads();
    #pragma unroll
    for (int i = 0; i < 32; i += 8)
        cat[(size_t)n * 49152 + (size_t)(s0 + ty + i) * 768 + 256 + w0 + tx] = tile[tx][ty + i];
}

// ---------------- copy x into the third slot of cat_at ------------------------
__global__ void copyx(const float* __restrict__ x, float* __restrict__ cat)
{
    int idx = blockIdx.x * blockDim.x + threadIdx.x;
    if (idx >= NN * SS * WWIN) return;
    int w = idx & 255;
    int s = (idx >> 8) & 63;
    int n = idx >> 14;
    cat[((size_t)n * SS + s) * 768 + 512 + w] = x[idx];
}

// ---------------- GRU recurrence ----------------------------------------------
__device__ __forceinline__ float sigmf(float x) { return 1.f / (1.f + expf(-x)); }

__global__ void gru_kernel(const float* __restrict__ giAll,
                           const float* __restrict__ Whh0, const float* __restrict__ bhh0,
                           const float* __restrict__ Wih1, const float* __restrict__ bih1,
                           const float* __restrict__ Whh1, const float* __restrict__ bhh1,
                           const float* __restrict__ Hpre,
                           float* __restrict__ gruOut, float* __restrict__ outCatH)
{
    int n = blockIdx.x;
    int tid = threadIdx.x;                 // 96 threads
    __shared__ float w0[96 * 33], wi1[96 * 33], wh1[96 * 33];
    __shared__ float h0s[32], h1s[32];
    __shared__ float gi0s[96], gh0s[96], gi1s[96], gh1s[96];

    for (int idx = tid; idx < 96 * 32; idx += 96) {
        int g = idx >> 5, j = idx & 31;
        w0 [g * 33 + j] = Whh0[(size_t)n * 3072 + idx];
        wi1[g * 33 + j] = Wih1[(size_t)n * 3072 + idx];
        wh1[g * 33 + j] = Whh1[(size_t)n * 3072 + idx];
    }
    if (tid < 32) {
        h0s[tid] = Hpre[(size_t)n * 32 + tid];
        h1s[tid] = Hpre[8192 + (size_t)n * 32 + tid];
    }
    float bh0v = bhh0[(size_t)n * 96 + tid];
    float bi1v = bih1[(size_t)n * 96 + tid];
    float bh1v = bhh1[(size_t)n * 96 + tid];
    __syncthreads();

    for (int t = 0; t < SS; t++) {
        float acc = bh0v;
        #pragma unroll
        for (int j = 0; j < 32; j++) acc += w0[tid * 33 + j] * h0s[j];
        gh0s[tid] = acc;
        gi0s[tid] = giAll[((size_t)n * SS + t) * 96 + tid];
        __syncthreads();
        if (tid < 32) {
            float r  = sigmf(gi0s[tid]      + gh0s[tid]);
            float z  = sigmf(gi0s[32 + tid] + gh0s[32 + tid]);
            float nn = tanhf(gi0s[64 + tid] + r * gh0s[64 + tid]);
            h0s[tid] = (1.f - z) * nn + z * h0s[tid];
        }
        __syncthreads();
        float a1 = bi1v, a2 = bh1v;
        #pragma unroll
        for (int j = 0; j < 32; j++) {
            a1 += wi1[tid * 33 + j] * h0s[j];
            a2 += wh1[tid * 33 + j] * h1s[j];
        }
        gi1s[tid] = a1; gh1s[tid] = a2;
        __syncthreads();
        if (tid < 32) {
            float r  = sigmf(gi1s[tid]      + gh1s[tid]);
            float z  = sigmf(gi1s[32 + tid] + gh1s[32 + tid]);
            float nn = tanhf(gi1s[64 + tid] + r * gh1s[64 + tid]);
            float h1n = (1.f - z) * nn + z * h1s[tid];
            h1s[tid] = h1n;
            gruOut[((size_t)n * SS + t) * 32 + tid] = h1n;
        }
        __syncthreads();
    }
    if (tid < 32) {
        outCatH[(size_t)n * 32 + tid]        = h0s[tid];
        outCatH[8192 + (size_t)n * 32 + tid] = h1s[tid];
    }
}

// ---------------- fused fc1+fc2+fc3 -------------------------------------------
__global__ void fc_fused(const float* __restrict__ gru,
                         const float* __restrict__ W1, const float* __restrict__ b1,
                         const float* __restrict__ W2, const float* __restrict__ b2,
                         const float* __restrict__ w3, const float* __restrict__ b3,
                         float* __restrict__ ct)
{
    int n = blockIdx.x;
    int tid = threadIdx.x;                 // 256
    int warp = tid >> 5, lane = tid & 31;
    __shared__ float W1s[32 * 33], W2s[32 * 33];
    __shared__ float w3s[32], b1s[32], b2s[32];
    __shared__ float xs[8][33];

    for (int idx = tid; idx < 1024; idx += 256) {
        int r = idx >> 5, c = idx & 31;
        W1s[r * 33 + c] = W1[(size_t)n * 1024 + idx];
        W2s[r * 33 + c] = W2[(size_t)n * 1024 + idx];
    }
    if (tid < 32) {
        w3s[tid] = w3[(size_t)n * 32 + tid];
        b1s[tid] = b1[(size_t)n * 32 + tid];
        b2s[tid] = b2[(size_t)n * 32 + tid];
    }
    __syncthreads();
    float b3v = b3[n];

    for (int s = warp; s < 64; s += 8) {
        float xv = gru[((size_t)n * 64 + s) * 32 + lane];
        xs[warp][lane] = xv;
        __syncwarp();
        float h1 = b1s[lane];
        #pragma unroll
        for (int j = 0; j < 32; j++) h1 += W1s[lane * 33 + j] * xs[warp][j];
        h1 = fmaxf(h1, 0.f);
        __syncwarp();
        xs[warp][lane] = h1;
        __syncwarp();
        float h2 = b2s[lane];
        #pragma unroll
        for (int j = 0; j < 32; j++) h2 += W2s[lane * 33 + j] * xs[warp][j];
        h2 = fmaxf(h2, 0.f);
        float p = h2 * w3s[lane];
        #pragma unroll
        for (int o = 16; o; o >>= 1) p += __shfl_xor_sync(0xffffffffu, p, o);
        if (lane == 0) ct[(size_t)n * 64 + s] = p + b3v;
        __syncwarp();
    }
}

// ---------------- launch -------------------------------------------------------
extern "C" void kernel_launch(void* const* d_in, const int* in_sizes, int n_in,
                              void* d_out, int out_size)
{
    const float* x     = (const float*)d_in[0];
    const float* Fadj  = (const float*)d_in[1];
    const float* Tadj  = (const float*)d_in[2];
    const float* adj   = (const float*)d_in[3];
    const float* Hpre  = (const float*)d_in[4];
    const float* FattW = (const float*)d_in[5];
    const float* Fatta = (const float*)d_in[6];
    const float* TattW = (const float*)d_in[7];
    const float* Tatta = (const float*)d_in[8];
    const float* Wih0  = (const float*)d_in[9];
    const float* Whh0  = (const float*)d_in[10];
    const float* bih0  = (const float*)d_in[11];
    const float* bhh0  = (const float*)d_in[12];
    const float* Wih1  = (const float*)d_in[13];
    const float* Whh1  = (const float*)d_in[14];
    const float* bih1  = (const float*)d_in[15];
    const float* bhh1  = (const float*)d_in[16];
    const float* fc1w  = (const float*)d_in[17];
    const float* fc1b  = (const float*)d_in[18];
    const float* fc2w  = (const float*)d_in[19];
    const float* fc2b  = (const float*)d_in[20];
    const float* fc3w  = (const float*)d_in[21];
    const float* fc3b  = (const float*)d_in[22];
    const float* oW    = (const float*)d_in[23];
    const float* oa    = (const float*)d_in[24];
    const float* o1W   = (const float*)d_in[25];
    const float* o1a   = (const float*)d_in[26];
    const float* o2W   = (const float*)d_in[27];
    const float* o2a   = (const float*)d_in[28];
    float* out = (float*)d_out;

    float *WhF, *WhT, *Tat, *cat, *PF, *PT, *gi, *gru, *ct, *cat2, *Wh2, *WhO, *WhO1, *F1, *F2;
    cudaGetSymbolAddress((void**)&WhF,  g_WhF);
    cudaGetSymbolAddress((void**)&WhT,  g_WhT);
    cudaGetSymbolAddress((void**)&Tat,  g_Tat);
    cudaGetSymbolAddress((void**)&cat,  g_cat);
    cudaGetSymbolAddress((void**)&PF,   g_PF);
    cudaGetSymbolAddress((void**)&PT,   g_PT);
    cudaGetSymbolAddress((void**)&gi,   g_gi);
    cudaGetSymbolAddress((void**)&gru,  g_gru);
    cudaGetSymbolAddress((void**)&ct,   g_ct);
    cudaGetSymbolAddress((void**)&cat2, g_cat2);
    cudaGetSymbolAddress((void**)&Wh2,  g_Wh2);
    cudaGetSymbolAddress((void**)&WhO,  g_WhO);
    cudaGetSymbolAddress((void**)&WhO1, g_WhO1);
    cudaGetSymbolAddress((void**)&F1,   g_F1);
    cudaGetSymbolAddress((void**)&F2,   g_F2);

    // ---- Feature GAT ----
    gemm_p2<64,128><<<dim3(2, 1, 256), 256>>>(x, FattW, nullptr, WhF, 64, 256, 256,
                                              16384LL, 256, 1,  65536LL, 256, 1,
                                              16384LL, 256, 0, 0);
    gat_f12<<<2048, 256>>>(WhF, Fatta, F1, F2, 64, 256, 512LL, 256 * 64);
    gat_softmax<<<dim3(8, 256), 256>>>(F1, F2, Fadj, 4096LL, 64, PF);
    gemm_p2<64,128><<<dim3(2, 1, 256), 256>>>(PF, WhF, nullptr, cat, 64, 256, 64,
                                              4096LL, 64, 1,  16384LL, 256, 1,
                                              49152LL, 768, 0, 0);

    // ---- Time GAT ----
    gemm_p2<128,64><<<dim3(1, 2, 256), 256>>>(x, TattW, nullptr, WhT, 256, 64, 64,
                                              16384LL, 1, 256,  4096LL, 64, 1,
                                              16384LL, 64, 0, 0);
    gat_f12<<<8192, 256>>>(WhT, Tatta, F1, F2, 256, 64, 128LL, 256 * 256);
    gat_softmax<<<dim3(32, 256), 256>>>(F1, F2, Tadj, 65536LL, 256, PT);
    gemm_p2<128,64><<<dim3(1, 2, 256), 256>>>(PT, WhT, nullptr, Tat, 256, 64, 256,
                                              65536LL, 256, 1,  16384LL, 64, 1,
                                              16384LL, 64, 0, 0);
    transpose_T<<<dim3(8, 2, 256), dim3(32, 8)>>>(Tat, cat);

    // ---- x -> cat[:, :, 512:768] ----
    copyx<<<16384, 256>>>(x, cat);

    // ---- GRU input projection ----
    gemm_p2<64,128><<<dim3(1, 1, 256), 256>>>(cat, Wih0, bih0, gi, 64, 96, 768,
                                              49152LL, 768, 1,  73728LL, 1, 768,
                                              6144LL, 96, 96, 0);

    // ---- GRU recurrence ----
    gru_kernel<<<256, 96>>>(gi, Whh0, bhh0, Wih1, bih1, Whh1, bhh1, Hpre,
                            gru, out + 16384);

    // ---- fused FC stack ----
    fc_fused<<<256, 256>>>(gru, fc1w, fc1b, fc2w, fc2b, fc3w, fc3b, ct);

    // ---- output GAT #1 ----
    gemm_p2<128,64><<<dim3(1, 2, 1), 256>>>(ct, oW, nullptr, WhO, 256, 64, 64,
                                            0LL, 64, 1,  0LL, 64, 1,  0LL, 64, 0, 0);
    gat_f12<<<32, 256>>>(WhO, oa, F1, F2, 256, 64, 0LL, 256);
    gat_attn<<<dim3(32, 1), 256>>>(WhO, F1, F2, adj, 0LL, 256, 64,
                                   cat2, 0LL, 0LL, 128, 1);

    // ---- output GAT #2 ----
    gemm_p2<128,64><<<dim3(1, 2, 1), 256>>>(ct, o1W, nullptr, WhO1, 256, 64, 64,
                                            0LL, 64, 1,  0LL, 64, 1,  0LL, 64, 0, 0);
    gat_f12<<<32, 256>>>(WhO1, o1a, F1, F2, 256, 64, 0LL, 256);
    gat_attn<<<dim3(32, 1), 256>>>(WhO1, F1, F2, adj, 0LL, 256, 64,
                                   cat2, 0LL, 64LL, 128, 1);

    // ---- final GAT -> d_out ----
    gemm_p2<128,64><<<dim3(1, 2, 1), 256>>>(cat2, o2W, nullptr, Wh2, 256, 64, 128,
                                            0LL, 128, 1,  0LL, 64, 1,  0LL, 64, 0, 0);
    gat_f12<<<32, 256>>>(Wh2, o2a, F1, F2, 256, 64, 0LL, 256);
    gat_attn<<<dim3(32, 1), 256>>>(Wh2, F1, F2, adj, 0LL, 256, 64,
                                   out, 0LL, 0LL, 64, 1);
}